// round 1
// baseline (speedup 1.0000x reference)
#include <cuda_runtime.h>

#define FULLMASK 0xffffffffu

struct C2 { float x, y; };

__device__ __forceinline__ C2 cmul(C2 a, C2 b){
    C2 r; r.x = a.x*b.x - a.y*b.y; r.y = a.x*b.y + a.y*b.x; return r;
}

// p[j] = state_at_lane(lane ^ L)[j ^ M]
template<int L, int M>
__device__ __forceinline__ void fetch_partner(const C2 st[8], C2 p[8]){
#pragma unroll
    for (int j = 0; j < 8; j++){
        C2 v = st[j ^ M];
        if constexpr (L != 0){
            v.x = __shfl_xor_sync(FULLMASK, v.x, L);
            v.y = __shfl_xor_sync(FULLMASK, v.y, L);
        }
        p[j] = v;
    }
}

// RXX: new[a] = c*old[a] - i*s*old[a^mask]
template<int L, int M>
__device__ __forceinline__ void rxx_gate(C2 st[8], float c, float s){
    C2 p[8]; fetch_partner<L, M>(st, p);
#pragma unroll
    for (int j = 0; j < 8; j++){
        C2 n;
        n.x = c*st[j].x + s*p[j].y;
        n.y = c*st[j].y - s*p[j].x;
        st[j] = n;
    }
}

// Generic (optionally controlled) 2x2 on target bit.
// tbit==0: new = m00*old + m01*partner ; tbit==1: new = m11*old + m10*partner
template<int TL, int TM, int CL, int CM>
__device__ __forceinline__ void gate2(C2 st[8], int lane, C2 m00, C2 m01, C2 m10, C2 m11){
    C2 p[8]; fetch_partner<TL, TM>(st, p);
#pragma unroll
    for (int j = 0; j < 8; j++){
        bool tbit = ((lane & TL) | (j & TM)) != 0;
        C2 a = tbit ? m11 : m00;
        C2 b = tbit ? m10 : m01;
        C2 n = cmul(a, st[j]);
        C2 t = cmul(b, p[j]);
        n.x += t.x; n.y += t.y;
        bool ctrl = ((CL | CM) == 0) || (((lane & CL) | (j & CM)) != 0);
        if (ctrl) st[j] = n;
    }
}

// CRZ: where control=1, multiply by e^{-i t/2} (tbit=0) or e^{+i t/2} (tbit=1)
template<int TL, int TM, int CL, int CM>
__device__ __forceinline__ void crz_gate(C2 st[8], int lane, float c, float s){
#pragma unroll
    for (int j = 0; j < 8; j++){
        bool tbit = ((lane & TL) | (j & TM)) != 0;
        bool ctrl = (((lane & CL) | (j & CM)) != 0);
        float ss = tbit ? s : -s;
        C2 n;
        n.x = c*st[j].x - ss*st[j].y;
        n.y = c*st[j].y + ss*st[j].x;
        if (ctrl) st[j] = n;
    }
}

template<int TYPE, int TL, int TM, int CL, int CM>
__device__ __forceinline__ void cr_gate(C2 st[8], int lane, float c, float s){
    if constexpr (TYPE == 0){        // CRX
        gate2<TL,TM,CL,CM>(st, lane, C2{c,0.f}, C2{0.f,-s}, C2{0.f,-s}, C2{c,0.f});
    } else if constexpr (TYPE == 1){ // CRY
        gate2<TL,TM,CL,CM>(st, lane, C2{c,0.f}, C2{-s,0.f}, C2{s,0.f}, C2{c,0.f});
    } else {                         // CRZ (diagonal, no partner traffic)
        crz_gate<TL,TM,CL,CM>(st, lane, c, s);
    }
}

template<int TL, int TM>
__device__ __forceinline__ void u3_gate(C2 st[8], int lane, const C2* m){
    gate2<TL,TM,0,0>(st, lane, m[0], m[1], m[2], m[3]);
}

// Wire -> bit map (wire w = amplitude bit 7-w):
//  w0:lane16  w1:lane8  w2:lane4  w3:lane2  w4:lane1  w5:loc4  w6:loc2  w7:loc1
template<int TYPE>
__device__ __forceinline__ void run_branch(const C2 base[8], int lane,
        const float* crc, const float* crs, const C2* u3m,
        float& z3, float& z7){
    C2 st[8];
#pragma unroll
    for (int j = 0; j < 8; j++) st[j] = base[j];
    // CR pairs A: (0,1)(2,3)(4,5)(6,7)(1,2)(3,4)(5,6)
    cr_gate<TYPE, 8,0, 16,0>(st, lane, crc[0], crs[0]);
    cr_gate<TYPE, 2,0,  4,0>(st, lane, crc[1], crs[1]);
    cr_gate<TYPE, 0,4,  1,0>(st, lane, crc[2], crs[2]);
    cr_gate<TYPE, 0,1,  0,2>(st, lane, crc[3], crs[3]);
    cr_gate<TYPE, 4,0,  8,0>(st, lane, crc[4], crs[4]);
    cr_gate<TYPE, 1,0,  2,0>(st, lane, crc[5], crs[5]);
    cr_gate<TYPE, 0,2,  0,4>(st, lane, crc[6], crs[6]);
    // U3 on wires 1,3,5,7
    u3_gate<8,0>(st, lane, u3m + 0);
    u3_gate<2,0>(st, lane, u3m + 4);
    u3_gate<0,4>(st, lane, u3m + 8);
    u3_gate<0,1>(st, lane, u3m + 12);
    // CR pairs B: (1,3)(5,7)(3,5)
    cr_gate<TYPE, 2,0, 8,0>(st, lane, crc[7], crs[7]);
    cr_gate<TYPE, 0,1, 0,4>(st, lane, crc[8], crs[8]);
    cr_gate<TYPE, 0,4, 2,0>(st, lane, crc[9], crs[9]);
    // U3 on wires 3,7
    u3_gate<2,0>(st, lane, u3m + 16);
    u3_gate<0,1>(st, lane, u3m + 20);
    // <Z3> (lane bit 1), <Z7> (local bit 0)
    float a3 = 0.f, a7 = 0.f;
#pragma unroll
    for (int j = 0; j < 8; j++){
        float pr = st[j].x*st[j].x + st[j].y*st[j].y;
        a3 += (lane & 2) ? -pr : pr;
        a7 += (j & 1) ? -pr : pr;
    }
#pragma unroll
    for (int o = 16; o; o >>= 1){
        a3 += __shfl_xor_sync(FULLMASK, a3, o);
        a7 += __shfl_xor_sync(FULLMASK, a7, o);
    }
    z3 = a3; z7 = a7;
}

__global__ void __launch_bounds__(256)
qcnn_kernel(const float* __restrict__ theta, const float* __restrict__ phi,
            const float* __restrict__ crw, const float* __restrict__ u3p,
            const float* __restrict__ W1, const float* __restrict__ b1,
            const float* __restrict__ W2, const float* __restrict__ b2,
            float* __restrict__ out, int n)
{
    __shared__ float s_crc[10], s_crs[10];
    __shared__ C2 s_u3[3*6*4];   // [branch][gate][m00,m01,m10,m11]
    __shared__ float s_W1[72], s_b1[12], s_W2[12], s_b2;

    int tid = threadIdx.x;
    if (tid < 10){
        float t = 0.5f * crw[tid];
        s_crc[tid] = cosf(t);
        s_crs[tid] = sinf(t);
    } else if (tid >= 32 && tid < 50){
        int g = tid - 32;   // branch*6 + gate
        float t  = u3p[g*3+0], ph = u3p[g*3+1], la = u3p[g*3+2];
        float ct, stt; sincosf(0.5f*t, &stt, &ct);
        float cl, sl;  sincosf(la,     &sl,  &cl);
        float cp, sp;  sincosf(ph,     &sp,  &cp);
        float cpl, spl; sincosf(ph+la, &spl, &cpl);
        s_u3[g*4+0] = C2{ct, 0.f};            // m00 = cos(t/2)
        s_u3[g*4+1] = C2{-cl*stt, -sl*stt};   // m01 = -e^{i lam} sin(t/2)
        s_u3[g*4+2] = C2{cp*stt,  sp*stt};    // m10 =  e^{i ph}  sin(t/2)
        s_u3[g*4+3] = C2{cpl*ct,  spl*ct};    // m11 =  e^{i(ph+lam)} cos(t/2)
    } else if (tid >= 64 && tid < 136)  s_W1[tid-64]  = W1[tid-64];
    else if (tid >= 160 && tid < 172)   s_b1[tid-160] = b1[tid-160];
    else if (tid >= 176 && tid < 188)   s_W2[tid-176] = W2[tid-176];
    else if (tid == 200)                s_b2 = b2[0];
    __syncthreads();

    int lane = tid & 31;
    int sample = blockIdx.x * 8 + (tid >> 5);
    if (sample >= n) return;

    float th = theta[sample], fi = phi[sample];
    float cth, sth; sincosf(th, &sth, &cth);

    // RZ layer (all 8 wires, half-angle phi) = diag phase e^{i*phi*(2*popc(a)-8)}.
    // For this lane: angle = alpha + 2*phi*popc(j), alpha = 2*phi*(popc(lane)-4).
    C2 z; sincosf(2.f*fi, &z.y, &z.x);
    int pcl = __popc(lane);
    C2 wk[4];
    sincosf(2.f*fi*(float)(pcl - 4), &wk[0].y, &wk[0].x);
    wk[1] = cmul(wk[0], z);
    wk[2] = cmul(wk[1], z);
    wk[3] = cmul(wk[2], z);

    C2 st[8];
#pragma unroll
    for (int j = 0; j < 8; j++) st[j] = C2{0.0625f, 0.f};

    const int pcj[8] = {0,1,1,2,1,2,2,3};
#pragma unroll 1
    for (int cyc = 0; cyc < 4; cyc++){
#pragma unroll
        for (int j = 0; j < 8; j++) st[j] = cmul(st[j], wk[pcj[j]]);
        // RXX pairs: (0,1)(2,3)(4,5)(6,7) then (1,2)(3,4)(5,6)
        rxx_gate<24,0>(st, cth, sth);
        rxx_gate< 6,0>(st, cth, sth);
        rxx_gate< 1,4>(st, cth, sth);
        rxx_gate< 0,3>(st, cth, sth);
        rxx_gate<12,0>(st, cth, sth);
        rxx_gate< 3,0>(st, cth, sth);
        rxx_gate< 0,6>(st, cth, sth);
    }

    float feat[6];
    run_branch<0>(st, lane, s_crc, s_crs, s_u3 + 0,  feat[0], feat[1]);
    run_branch<1>(st, lane, s_crc, s_crs, s_u3 + 24, feat[2], feat[3]);
    run_branch<2>(st, lane, s_crc, s_crs, s_u3 + 48, feat[4], feat[5]);

    if (lane == 0){
        float acc = s_b2;
#pragma unroll
        for (int k = 0; k < 12; k++){
            float u = s_b1[k];
#pragma unroll
            for (int i = 0; i < 6; i++) u += s_W1[k*6+i] * feat[i];
            acc += s_W2[k] * tanhf(u);
        }
        out[sample] = 1.f / (1.f + expf(-acc));
    }
}

extern "C" void kernel_launch(void* const* d_in, const int* in_sizes, int n_in,
                              void* d_out, int out_size)
{
    const float* theta = (const float*)d_in[0];
    const float* phi   = (const float*)d_in[1];
    const float* crw   = (const float*)d_in[2];
    const float* u3p   = (const float*)d_in[3];
    const float* W1    = (const float*)d_in[4];
    const float* b1    = (const float*)d_in[5];
    const float* W2    = (const float*)d_in[6];
    const float* b2    = (const float*)d_in[7];
    float* out = (float*)d_out;
    int n = in_sizes[0];
    int blocks = (n + 7) / 8;
    qcnn_kernel<<<blocks, 256>>>(theta, phi, crw, u3p, W1, b1, W2, b2, out, n);
}

// round 2
// speedup vs baseline: 1.0477x; 1.0477x over previous
#include <cuda_runtime.h>

#define FULLMASK 0xffffffffu

struct C2 { float x, y; };

__device__ __forceinline__ C2 cmul(C2 a, C2 b){
    C2 r; r.x = a.x*b.x - a.y*b.y; r.y = a.x*b.y + a.y*b.x; return r;
}

// p[j] = state_at_lane(lane ^ L)[j ^ M]
template<int L, int M>
__device__ __forceinline__ void fetch_partner(const C2 st[8], C2 p[8]){
#pragma unroll
    for (int j = 0; j < 8; j++){
        C2 v = st[j ^ M];
        if constexpr (L != 0){
            v.x = __shfl_xor_sync(FULLMASK, v.x, L);
            v.y = __shfl_xor_sync(FULLMASK, v.y, L);
        }
        p[j] = v;
    }
}

// RXX: new[a] = c*old[a] - i*s*old[a^mask]
template<int L, int M>
__device__ __forceinline__ void rxx_gate(C2 st[8], float c, float s){
    C2 p[8]; fetch_partner<L, M>(st, p);
#pragma unroll
    for (int j = 0; j < 8; j++){
        C2 n;
        n.x = c*st[j].x + s*p[j].y;
        n.y = c*st[j].y - s*p[j].x;
        st[j] = n;
    }
}

// CRX where ctrl=1: new = c*old - i*s*partner   (tbit-symmetric)
template<int TL, int TM, int CL, int CM>
__device__ __forceinline__ void crx_gate(C2 st[8], int lane, float c, float s){
    C2 p[8]; fetch_partner<TL, TM>(st, p);
#pragma unroll
    for (int j = 0; j < 8; j++){
        bool ctrl = (((lane & CL) | (j & CM)) != 0);
        C2 n;
        n.x = c*st[j].x + s*p[j].y;
        n.y = c*st[j].y - s*p[j].x;
        if (ctrl) st[j] = n;
    }
}

// CRY where ctrl=1: tbit0: c*old - s*p ; tbit1: c*old + s*p
template<int TL, int TM, int CL, int CM>
__device__ __forceinline__ void cry_gate(C2 st[8], int lane, float c, float s){
    C2 p[8]; fetch_partner<TL, TM>(st, p);
#pragma unroll
    for (int j = 0; j < 8; j++){
        bool tb = (((lane & TL) | (j & TM)) != 0);
        bool ctrl = (((lane & CL) | (j & CM)) != 0);
        float sel = tb ? s : -s;
        C2 n;
        n.x = c*st[j].x + sel*p[j].x;
        n.y = c*st[j].y + sel*p[j].y;
        if (ctrl) st[j] = n;
    }
}

// U3 via ZYZ: diag(1,e^{i phi}) * RY(t) * diag(1,e^{i lam})
// g = {c, s, el.x, el.y, ep.x, ep.y}
template<int TL, int TM>
__device__ __forceinline__ void u3_gate(C2 st[8], int lane, const float* g){
    float c = g[0], s = g[1];
    C2 el{g[2], g[3]}, ep{g[4], g[5]};
#pragma unroll
    for (int j = 0; j < 8; j++){
        bool tb = (((lane & TL) | (j & TM)) != 0);
        C2 t = cmul(st[j], el);
        if (tb) st[j] = t;
    }
    C2 p[8]; fetch_partner<TL, TM>(st, p);
#pragma unroll
    for (int j = 0; j < 8; j++){
        bool tb = (((lane & TL) | (j & TM)) != 0);
        float sel = tb ? s : -s;
        C2 n;
        n.x = c*st[j].x + sel*p[j].x;
        n.y = c*st[j].y + sel*p[j].y;
        C2 t = cmul(n, ep);
        st[j] = tb ? t : n;
    }
}

__device__ __forceinline__ void measure(const C2 st[8], int lane, float& z3, float& z7){
    float a3 = 0.f, a7 = 0.f;
#pragma unroll
    for (int j = 0; j < 8; j++){
        float pr = st[j].x*st[j].x + st[j].y*st[j].y;
        a3 += (lane & 2) ? -pr : pr;
        a7 += (j & 1) ? -pr : pr;
    }
#pragma unroll
    for (int o = 16; o; o >>= 1){
        a3 += __shfl_xor_sync(FULLMASK, a3, o);
        a7 += __shfl_xor_sync(FULLMASK, a7, o);
    }
    z3 = a3; z7 = a7;
}

// Wire -> bit map (wire w = amplitude bit 7-w):
//  w0:lane16  w1:lane8  w2:lane4  w3:lane2  w4:lane1  w5:loc4  w6:loc2  w7:loc1
template<int TYPE>  // 0 = CRX, 1 = CRY
__device__ __forceinline__ void run_branch_xy(const C2 base[8], int lane,
        const float* crc, const float* crs, const float* u3g,
        float& z3, float& z7){
    C2 st[8];
#pragma unroll
    for (int j = 0; j < 8; j++) st[j] = base[j];
#define CRG(TL,TM,CL,CM,i) \
    if constexpr (TYPE == 0) crx_gate<TL,TM,CL,CM>(st, lane, crc[i], crs[i]); \
    else                     cry_gate<TL,TM,CL,CM>(st, lane, crc[i], crs[i]);
    // CR pairs A: (0,1)(2,3)(4,5)(6,7)(1,2)(3,4)(5,6)
    CRG( 8,0, 16,0, 0)
    CRG( 2,0,  4,0, 1)
    CRG( 0,4,  1,0, 2)
    CRG( 0,1,  0,2, 3)
    CRG( 4,0,  8,0, 4)
    CRG( 1,0,  2,0, 5)
    CRG( 0,2,  0,4, 6)
    // U3 on wires 1,3,5,7
    u3_gate<8,0>(st, lane, u3g + 0*6);
    u3_gate<2,0>(st, lane, u3g + 1*6);
    u3_gate<0,4>(st, lane, u3g + 2*6);
    u3_gate<0,1>(st, lane, u3g + 3*6);
    // CR pairs B: (1,3)(5,7)(3,5)
    CRG( 2,0,  8,0, 7)
    CRG( 0,1,  0,4, 8)
    CRG( 0,4,  2,0, 9)
#undef CRG
    // U3 on wires 3,7
    u3_gate<2,0>(st, lane, u3g + 4*6);
    u3_gate<0,1>(st, lane, u3g + 5*6);
    measure(st, lane, z3, z7);
}

// CRZ branch: all 10 CR gates are diagonal -> two precomputed phase tables.
__device__ __forceinline__ void run_branch_z(const C2 base[8], int lane,
        const C2* phA, const C2* phB, const float* u3g,
        float& z3, float& z7){
    C2 st[8];
#pragma unroll
    for (int j = 0; j < 8; j++) st[j] = cmul(base[j], phA[j*32 + lane]);
    u3_gate<8,0>(st, lane, u3g + 0*6);
    u3_gate<2,0>(st, lane, u3g + 1*6);
    u3_gate<0,4>(st, lane, u3g + 2*6);
    u3_gate<0,1>(st, lane, u3g + 3*6);
#pragma unroll
    for (int j = 0; j < 8; j++) st[j] = cmul(st[j], phB[j*32 + lane]);
    u3_gate<2,0>(st, lane, u3g + 4*6);
    u3_gate<0,1>(st, lane, u3g + 5*6);
    measure(st, lane, z3, z7);
}

__global__ void __launch_bounds__(256)
qcnn_kernel(const float* __restrict__ theta, const float* __restrict__ phi,
            const float* __restrict__ crw, const float* __restrict__ u3p,
            const float* __restrict__ W1, const float* __restrict__ b1,
            const float* __restrict__ W2, const float* __restrict__ b2,
            float* __restrict__ out, int n)
{
    __shared__ float s_crc[10], s_crs[10];
    __shared__ float s_u3[18*6];          // per gate: c, s, el.x, el.y, ep.x, ep.y
    __shared__ float s_W1[72], s_b1[12], s_W2[12], s_b2;
    __shared__ C2 s_phA[256], s_phB[256]; // CRZ diag phases, [j][lane] layout

    int tid = threadIdx.x;
    if (tid < 10){
        float t = 0.5f * crw[tid];
        s_crc[tid] = cosf(t);
        s_crs[tid] = sinf(t);
    } else if (tid >= 32 && tid < 50){
        int g = tid - 32;   // branch*6 + gate
        float t  = u3p[g*3+0], ph = u3p[g*3+1], la = u3p[g*3+2];
        float ct, stt; sincosf(0.5f*t, &stt, &ct);
        float cl, sl;  sincosf(la,     &sl,  &cl);
        float cp, sp;  sincosf(ph,     &sp,  &cp);
        s_u3[g*6+0] = ct;  s_u3[g*6+1] = stt;
        s_u3[g*6+2] = cl;  s_u3[g*6+3] = sl;
        s_u3[g*6+4] = cp;  s_u3[g*6+5] = sp;
    } else if (tid >= 64 && tid < 136)  s_W1[tid-64]  = W1[tid-64];
    else if (tid >= 160 && tid < 172)   s_b1[tid-160] = b1[tid-160];
    else if (tid >= 176 && tid < 188)   s_W2[tid-176] = W2[tid-176];
    else if (tid == 200)                s_b2 = b2[0];
    __syncthreads();

    // Build CRZ phase tables: amplitude a = tid; bit of wire w is (a >> (7-w)) & 1.
    {
        int a = tid;
        C2 pA{1.f, 0.f}, pB{1.f, 0.f};
#define CRZF(P, cw, tw, i) \
        if ((a >> (7-(cw))) & 1){ \
            float ss = ((a >> (7-(tw))) & 1) ? s_crs[i] : -s_crs[i]; \
            P = cmul(P, C2{s_crc[i], ss}); \
        }
        CRZF(pA, 0,1, 0) CRZF(pA, 2,3, 1) CRZF(pA, 4,5, 2) CRZF(pA, 6,7, 3)
        CRZF(pA, 1,2, 4) CRZF(pA, 3,4, 5) CRZF(pA, 5,6, 6)
        CRZF(pB, 1,3, 7) CRZF(pB, 5,7, 8) CRZF(pB, 3,5, 9)
#undef CRZF
        s_phA[(a & 7)*32 + (a >> 3)] = pA;
        s_phB[(a & 7)*32 + (a >> 3)] = pB;
    }
    __syncthreads();

    int lane = tid & 31;
    int sample = blockIdx.x * 8 + (tid >> 5);
    if (sample >= n) return;

    float th = theta[sample], fi = phi[sample];
    float cth, sth; sincosf(th, &sth, &cth);

    // RZ layer (all 8 wires, half-angle phi) = diag phase e^{i*phi*(2*popc(a)-8)}.
    C2 z; sincosf(2.f*fi, &z.y, &z.x);
    int pcl = __popc(lane);
    C2 wk[4];
    sincosf(2.f*fi*(float)(pcl - 4), &wk[0].y, &wk[0].x);
    wk[1] = cmul(wk[0], z);
    wk[2] = cmul(wk[1], z);
    wk[3] = cmul(wk[2], z);

    C2 st[8];
#pragma unroll
    for (int j = 0; j < 8; j++) st[j] = C2{0.0625f, 0.f};

    const int pcj[8] = {0,1,1,2,1,2,2,3};
#pragma unroll 1
    for (int cyc = 0; cyc < 4; cyc++){
#pragma unroll
        for (int j = 0; j < 8; j++) st[j] = cmul(st[j], wk[pcj[j]]);
        // RXX pairs: (0,1)(2,3)(4,5)(6,7) then (1,2)(3,4)(5,6)
        rxx_gate<24,0>(st, cth, sth);
        rxx_gate< 6,0>(st, cth, sth);
        rxx_gate< 1,4>(st, cth, sth);
        rxx_gate< 0,3>(st, cth, sth);
        rxx_gate<12,0>(st, cth, sth);
        rxx_gate< 3,0>(st, cth, sth);
        rxx_gate< 0,6>(st, cth, sth);
    }

    float feat[6];
    run_branch_xy<0>(st, lane, s_crc, s_crs, s_u3 + 0,   feat[0], feat[1]);
    run_branch_xy<1>(st, lane, s_crc, s_crs, s_u3 + 36,  feat[2], feat[3]);
    run_branch_z(st, lane, s_phA, s_phB, s_u3 + 72, feat[4], feat[5]);

    if (lane == 0){
        float acc = s_b2;
#pragma unroll
        for (int k = 0; k < 12; k++){
            float u = s_b1[k];
#pragma unroll
            for (int i = 0; i < 6; i++) u += s_W1[k*6+i] * feat[i];
            acc += s_W2[k] * tanhf(u);
        }
        out[sample] = 1.f / (1.f + expf(-acc));
    }
}

extern "C" void kernel_launch(void* const* d_in, const int* in_sizes, int n_in,
                              void* d_out, int out_size)
{
    const float* theta = (const float*)d_in[0];
    const float* phi   = (const float*)d_in[1];
    const float* crw   = (const float*)d_in[2];
    const float* u3p   = (const float*)d_in[3];
    const float* W1    = (const float*)d_in[4];
    const float* b1    = (const float*)d_in[5];
    const float* W2    = (const float*)d_in[6];
    const float* b2    = (const float*)d_in[7];
    float* out = (float*)d_out;
    int n = in_sizes[0];
    int blocks = (n + 7) / 8;
    qcnn_kernel<<<blocks, 256>>>(theta, phi, crw, u3p, W1, b1, W2, b2, out, n);
}

// round 3
// speedup vs baseline: 1.2069x; 1.1520x over previous
#include <cuda_runtime.h>

#define FULLMASK 0xffffffffu

struct C2 { float x, y; };

__device__ __forceinline__ C2 cmul(C2 a, C2 b){
    C2 r; r.x = a.x*b.x - a.y*b.y; r.y = a.x*b.y + a.y*b.x; return r;
}

// p[j] = state_at_lane(lane ^ L)[j ^ M]
template<int L, int M>
__device__ __forceinline__ void fetch_partner(const C2 st[8], C2 p[8]){
#pragma unroll
    for (int j = 0; j < 8; j++){
        C2 v = st[j ^ M];
        if constexpr (L != 0){
            v.x = __shfl_xor_sync(FULLMASK, v.x, L);
            v.y = __shfl_xor_sync(FULLMASK, v.y, L);
        }
        p[j] = v;
    }
}

// RXX: new[a] = c*old[a] - i*s*old[a^mask]
template<int L, int M>
__device__ __forceinline__ void rxx_gate(C2 st[8], float c, float s){
    C2 p[8]; fetch_partner<L, M>(st, p);
#pragma unroll
    for (int j = 0; j < 8; j++){
        C2 n;
        n.x = c*st[j].x + s*p[j].y;
        n.y = c*st[j].y - s*p[j].x;
        st[j] = n;
    }
}

// CRX where ctrl=1: new = c*old - i*s*partner   (tbit-symmetric)
template<int TL, int TM, int CL, int CM>
__device__ __forceinline__ void crx_gate(C2 st[8], int lane, float c, float s){
    C2 p[8]; fetch_partner<TL, TM>(st, p);
#pragma unroll
    for (int j = 0; j < 8; j++){
        bool ctrl = (((lane & CL) | (j & CM)) != 0);
        if ((CM == 0) || ctrl){   // reg-bit ctrl: compile-time dead for half the j's
            C2 n;
            n.x = c*st[j].x + s*p[j].y;
            n.y = c*st[j].y - s*p[j].x;
            if (ctrl) st[j] = n;
        }
    }
}

// CRY where ctrl=1: tbit0: c*old - s*p ; tbit1: c*old + s*p
template<int TL, int TM, int CL, int CM>
__device__ __forceinline__ void cry_gate(C2 st[8], int lane, float c, float s){
    C2 p[8]; fetch_partner<TL, TM>(st, p);
#pragma unroll
    for (int j = 0; j < 8; j++){
        bool ctrl = (((lane & CL) | (j & CM)) != 0);
        if ((CM == 0) || ctrl){
            bool tb = (((lane & TL) | (j & TM)) != 0);
            float sel = tb ? s : -s;
            C2 n;
            n.x = c*st[j].x + sel*p[j].x;
            n.y = c*st[j].y + sel*p[j].y;
            if (ctrl) st[j] = n;
        }
    }
}

// U3 direct 2x2: m = [m00(real), m01; m10, m11] stored as 4 C2 in smem.
template<int TL, int TM>
__device__ __forceinline__ void u3_gate(C2 st[8], int lane, const C2* m){
    float4 q0 = *(const float4*)(m);      // m00r, 0, m01.x, m01.y
    float4 q1 = *(const float4*)(m + 2);  // m10.x, m10.y, m11.x, m11.y
    C2 p[8]; fetch_partner<TL, TM>(st, p);
#pragma unroll
    for (int j = 0; j < 8; j++){
        bool tb = (((lane & TL) | (j & TM)) != 0);
        float ax = tb ? q1.z : q0.x;
        float ay = tb ? q1.w : 0.f;
        float bx = tb ? q1.x : q0.z;
        float by = tb ? q1.y : q0.w;
        C2 n;
        n.x = ax*st[j].x - ay*st[j].y + bx*p[j].x - by*p[j].y;
        n.y = ax*st[j].y + ay*st[j].x + bx*p[j].y + by*p[j].x;
        st[j] = n;
    }
}

// Signs are compile-time: Z3 -> reg bit 2, Z7 -> reg bit 1 (post-remap map).
__device__ __forceinline__ void measure(const C2 st[8], int lane, float& z3, float& z7){
    float a3 = 0.f, a7 = 0.f;
#pragma unroll
    for (int j = 0; j < 8; j++){
        float pr = st[j].x*st[j].x + st[j].y*st[j].y;
        a3 += (j & 2) ? -pr : pr;
        a7 += (j & 1) ? -pr : pr;
    }
#pragma unroll
    for (int o = 16; o; o >>= 1){
        a3 += __shfl_xor_sync(FULLMASK, a3, o);
        a7 += __shfl_xor_sync(FULLMASK, a7, o);
    }
    z3 = a3; z7 = a7;
}

// ── Branch-phase wire map (after w3<->w6 swap) ──
//  lanes: w0:16  w1:8  w2:4  w6:2  w4:1     regs: w5:4  w3:2  w7:1
template<int TYPE>  // 0 = CRX, 1 = CRY
__device__ __forceinline__ void run_branch_xy(const C2 base[8], int lane,
        const float* crc, const float* crs, const C2* u3m,
        float& z3, float& z7){
    C2 st[8];
#pragma unroll
    for (int j = 0; j < 8; j++) st[j] = base[j];
#define CRG(TL,TM,CL,CM,i) \
    if constexpr (TYPE == 0) crx_gate<TL,TM,CL,CM>(st, lane, crc[i], crs[i]); \
    else                     cry_gate<TL,TM,CL,CM>(st, lane, crc[i], crs[i]);
    // CR pairs A: (0,1)(2,3)(4,5)(6,7)(1,2)(3,4)(5,6)
    CRG( 8,0, 16,0, 0)   // (0,1)
    CRG( 0,2,  4,0, 1)   // (2,3)
    CRG( 0,4,  1,0, 2)   // (4,5)
    CRG( 0,1,  2,0, 3)   // (6,7)
    CRG( 4,0,  8,0, 4)   // (1,2)
    CRG( 1,0,  0,2, 5)   // (3,4)
    CRG( 2,0,  0,4, 6)   // (5,6)
    // U3 on wires 1,3,5,7
    u3_gate<8,0>(st, lane, u3m + 0*4);
    u3_gate<0,2>(st, lane, u3m + 1*4);
    u3_gate<0,4>(st, lane, u3m + 2*4);
    u3_gate<0,1>(st, lane, u3m + 3*4);
    // CR pairs B: (1,3)(5,7)(3,5)
    CRG( 0,2,  8,0, 7)
    CRG( 0,1,  0,4, 8)
    CRG( 0,4,  0,2, 9)
#undef CRG
    // U3 on wires 3,7
    u3_gate<0,2>(st, lane, u3m + 4*4);
    u3_gate<0,1>(st, lane, u3m + 5*4);
    measure(st, lane, z3, z7);
}

// CRZ branch: diagonal CR layers -> two precomputed phase tables.
__device__ __forceinline__ void run_branch_z(const C2 base[8], int lane,
        const C2* phA, const C2* phB, const C2* u3m,
        float& z3, float& z7){
    C2 st[8];
#pragma unroll
    for (int j = 0; j < 8; j++) st[j] = cmul(base[j], phA[j*32 + lane]);
    u3_gate<8,0>(st, lane, u3m + 0*4);
    u3_gate<0,2>(st, lane, u3m + 1*4);
    u3_gate<0,4>(st, lane, u3m + 2*4);
    u3_gate<0,1>(st, lane, u3m + 3*4);
#pragma unroll
    for (int j = 0; j < 8; j++) st[j] = cmul(st[j], phB[j*32 + lane]);
    u3_gate<0,2>(st, lane, u3m + 4*4);
    u3_gate<0,1>(st, lane, u3m + 5*4);
    measure(st, lane, z3, z7);
}

__global__ void __launch_bounds__(256)
qcnn_kernel(const float* __restrict__ theta, const float* __restrict__ phi,
            const float* __restrict__ crw, const float* __restrict__ u3p,
            const float* __restrict__ W1, const float* __restrict__ b1,
            const float* __restrict__ W2, const float* __restrict__ b2,
            float* __restrict__ out, int n)
{
    __shared__ float s_crc[10], s_crs[10];
    __shared__ C2 s_u3[18*4];             // per gate: {m00r,0},{m01},{m10},{m11}
    __shared__ float s_W1[72], s_b1[12], s_W2[12], s_b2;
    __shared__ C2 s_phA[256], s_phB[256]; // CRZ diag phases, [j][lane] (post-remap)

    int tid = threadIdx.x;
    if (tid < 10){
        float t = 0.5f * crw[tid];
        s_crc[tid] = cosf(t);
        s_crs[tid] = sinf(t);
    } else if (tid >= 32 && tid < 50){
        int g = tid - 32;   // branch*6 + gate
        float t  = u3p[g*3+0], ph = u3p[g*3+1], la = u3p[g*3+2];
        float ct, stt; sincosf(0.5f*t, &stt, &ct);
        float cl, sl;  sincosf(la,     &sl,  &cl);
        float cp, sp;  sincosf(ph,     &sp,  &cp);
        s_u3[g*4+0] = C2{ct, 0.f};                      // m00 (real)
        s_u3[g*4+1] = C2{-cl*stt, -sl*stt};             // m01 = -e^{i la} sin
        s_u3[g*4+2] = C2{cp*stt,  sp*stt};              // m10 =  e^{i ph} sin
        s_u3[g*4+3] = C2{(cp*cl - sp*sl)*ct, (cp*sl + sp*cl)*ct}; // m11
    } else if (tid >= 64 && tid < 136)  s_W1[tid-64]  = W1[tid-64];
    else if (tid >= 160 && tid < 172)   s_b1[tid-160] = b1[tid-160];
    else if (tid >= 176 && tid < 188)   s_W2[tid-176] = W2[tid-176];
    else if (tid == 200)                s_b2 = b2[0];
    __syncthreads();

    // CRZ phase tables. Amplitude a = tid, wire w bit = (a >> (7-w)) & 1.
    // Post-remap storage: lane = w0<<4|w1<<3|w2<<2|w6<<1|w4 ; j = w5<<2|w3<<1|w7
    {
        int a = tid;
        C2 pA{1.f, 0.f}, pB{1.f, 0.f};
#define CRZF(P, cw, tw, i) \
        if ((a >> (7-(cw))) & 1){ \
            float ss = ((a >> (7-(tw))) & 1) ? s_crs[i] : -s_crs[i]; \
            P = cmul(P, C2{s_crc[i], ss}); \
        }
        CRZF(pA, 0,1, 0) CRZF(pA, 2,3, 1) CRZF(pA, 4,5, 2) CRZF(pA, 6,7, 3)
        CRZF(pA, 1,2, 4) CRZF(pA, 3,4, 5) CRZF(pA, 5,6, 6)
        CRZF(pB, 1,3, 7) CRZF(pB, 5,7, 8) CRZF(pB, 3,5, 9)
#undef CRZF
        int w0=(a>>7)&1, w1=(a>>6)&1, w2=(a>>5)&1, w3=(a>>4)&1;
        int w4=(a>>3)&1, w5=(a>>2)&1, w6=(a>>1)&1, w7=a&1;
        int ln = (w0<<4)|(w1<<3)|(w2<<2)|(w6<<1)|w4;
        int jj = (w5<<2)|(w3<<1)|w7;
        s_phA[jj*32 + ln] = pA;
        s_phB[jj*32 + ln] = pB;
    }
    __syncthreads();

    int lane = tid & 31;
    int sample = blockIdx.x * 8 + (tid >> 5);
    if (sample >= n) return;

    float th = theta[sample], fi = phi[sample];
    float cth, sth; sincosf(th, &sth, &cth);

    // RZ layer = diag phase e^{i*phi*(2*popc(a)-8)} (loop map: w0-4 lanes, w5-7 regs)
    C2 z; sincosf(2.f*fi, &z.y, &z.x);
    int pcl = __popc(lane);
    C2 wk[4];
    sincosf(2.f*fi*(float)(pcl - 4), &wk[0].y, &wk[0].x);
    wk[1] = cmul(wk[0], z);
    wk[2] = cmul(wk[1], z);
    wk[3] = cmul(wk[2], z);

    C2 st[8];
#pragma unroll
    for (int j = 0; j < 8; j++) st[j] = C2{0.0625f, 0.f};

    const int pcj[8] = {0,1,1,2,1,2,2,3};
#pragma unroll 1
    for (int cyc = 0; cyc < 4; cyc++){
#pragma unroll
        for (int j = 0; j < 8; j++) st[j] = cmul(st[j], wk[pcj[j]]);
        // Loop map: w0:16 w1:8 w2:4 w3:2 w4:1 | w5:4 w6:2 w7:1
        rxx_gate<24,0>(st, cth, sth);  // (0,1)
        rxx_gate< 6,0>(st, cth, sth);  // (2,3)
        rxx_gate< 1,4>(st, cth, sth);  // (4,5)
        rxx_gate< 0,3>(st, cth, sth);  // (6,7)
        rxx_gate<12,0>(st, cth, sth);  // (1,2)
        rxx_gate< 3,0>(st, cth, sth);  // (3,4)
        rxx_gate< 0,6>(st, cth, sth);  // (5,6)
    }

    // Remap: swap wire 3 (lane bit 2) <-> wire 6 (reg bit 2). 8 shuffles.
#pragma unroll
    for (int j0i = 0; j0i < 4; j0i++){
        const int j0 = (j0i & 1) | ((j0i & 2) << 1);  // {0,1,4,5}
        const int jh = j0 | 2;
        bool hi = (lane & 2) != 0;
        C2 send = hi ? st[j0] : st[jh];
        send.x = __shfl_xor_sync(FULLMASK, send.x, 2);
        send.y = __shfl_xor_sync(FULLMASK, send.y, 2);
        if (hi) st[j0] = send; else st[jh] = send;
    }

    float feat[6];
    run_branch_xy<0>(st, lane, s_crc, s_crs, s_u3 + 0,   feat[0], feat[1]);
    run_branch_xy<1>(st, lane, s_crc, s_crs, s_u3 + 24,  feat[2], feat[3]);
    run_branch_z(st, lane, s_phA, s_phB, s_u3 + 48, feat[4], feat[5]);

    if (lane == 0){
        float acc = s_b2;
#pragma unroll
        for (int k = 0; k < 12; k++){
            float u = s_b1[k];
#pragma unroll
            for (int i = 0; i < 6; i++) u += s_W1[k*6+i] * feat[i];
            acc += s_W2[k] * tanhf(u);
        }
        out[sample] = 1.f / (1.f + expf(-acc));
    }
}

extern "C" void kernel_launch(void* const* d_in, const int* in_sizes, int n_in,
                              void* d_out, int out_size)
{
    const float* theta = (const float*)d_in[0];
    const float* phi   = (const float*)d_in[1];
    const float* crw   = (const float*)d_in[2];
    const float* u3p   = (const float*)d_in[3];
    const float* W1    = (const float*)d_in[4];
    const float* b1    = (const float*)d_in[5];
    const float* W2    = (const float*)d_in[6];
    const float* b2    = (const float*)d_in[7];
    float* out = (float*)d_out;
    int n = in_sizes[0];
    int blocks = (n + 7) / 8;
    qcnn_kernel<<<blocks, 256>>>(theta, phi, crw, u3p, W1, b1, W2, b2, out, n);
}

// round 6
// speedup vs baseline: 1.3391x; 1.1095x over previous
#include <cuda_runtime.h>

#define FULLMASK 0xffffffffu

struct alignas(8) C2 { float x, y; };

__device__ __forceinline__ C2 cmul(C2 a, C2 b){
    C2 r; r.x = a.x*b.x - a.y*b.y; r.y = a.x*b.y + a.y*b.x; return r;
}

// d = vc (.) s + vs (.) p   (elementwise f32x2: 1 mul + 1 fma packed)
__device__ __forceinline__ C2 pp2(C2 vc, C2 s, C2 vs, C2 p){
    C2 d;
    asm("{\n\t"
        ".reg .b64 t0, t1, t2, t3;\n\t"
        "mov.b64 t0, {%2,%3};\n\t"
        "mov.b64 t1, {%4,%5};\n\t"
        "mov.b64 t2, {%6,%7};\n\t"
        "mov.b64 t3, {%8,%9};\n\t"
        "mul.rn.f32x2 t2, t2, t3;\n\t"
        "fma.rn.f32x2 t0, t0, t1, t2;\n\t"
        "mov.b64 {%0,%1}, t0;\n\t"
        "}"
        : "=f"(d.x), "=f"(d.y)
        : "f"(vc.x),"f"(vc.y),"f"(s.x),"f"(s.y),
          "f"(vs.x),"f"(vs.y),"f"(p.x),"f"(p.y));
    return d;
}

__device__ __forceinline__ C2 padd(C2 a, C2 b){
    C2 d;
    asm("{\n\t"
        ".reg .b64 t0, t1;\n\t"
        "mov.b64 t0, {%2,%3};\n\t"
        "mov.b64 t1, {%4,%5};\n\t"
        "add.rn.f32x2 t0, t0, t1;\n\t"
        "mov.b64 {%0,%1}, t0;\n\t"
        "}"
        : "=f"(d.x), "=f"(d.y)
        : "f"(a.x),"f"(a.y),"f"(b.x),"f"(b.y));
    return d;
}

// Packed CR-style gate: st[j] = vc(.)st[j] + vs(.)partner, partner = st[j^TM] at lane^TL,
// optionally component-swapped (swap is free: absorbed into the asm pack).
// CM != 0: only amplitudes with (j & CM) are updated (uniform across lanes).
template<int TL, int TM, int CM, bool SWAP>
__device__ __forceinline__ void cr_packed(C2 st[8], C2 vc, C2 vs){
    C2 p[8];
#pragma unroll
    for (int j = 0; j < 8; j++){
        if (CM == 0 || (j & CM)){
            C2 v = st[j ^ TM];
            if (SWAP){ float t = v.x; v.x = v.y; v.y = t; }
            if (TL){
                v.x = __shfl_xor_sync(FULLMASK, v.x, TL);
                v.y = __shfl_xor_sync(FULLMASK, v.y, TL);
            }
            p[j] = v;
        }
    }
#pragma unroll
    for (int j = 0; j < 8; j++)
        if (CM == 0 || (j & CM)) st[j] = pp2(vc, st[j], vs, p[j]);
}

// CRY on a register-target bit: sign of vs depends on j&TM (compile time).
template<int TM, int CM>
__device__ __forceinline__ void cry_reg(C2 st[8], C2 vc, C2 vsp, C2 vsm){
    C2 p[8];
#pragma unroll
    for (int j = 0; j < 8; j++)
        if (CM == 0 || (j & CM)) p[j] = st[j ^ TM];
#pragma unroll
    for (int j = 0; j < 8; j++)
        if (CM == 0 || (j & CM)) st[j] = pp2(vc, st[j], (j & TM) ? vsp : vsm, p[j]);
}

// normal (unswapped) partner fetch for U3
template<int L, int M>
__device__ __forceinline__ void fetch_partner(const C2 st[8], C2 p[8]){
#pragma unroll
    for (int j = 0; j < 8; j++){
        C2 v = st[j ^ M];
        if constexpr (L != 0){
            v.x = __shfl_xor_sync(FULLMASK, v.x, L);
            v.y = __shfl_xor_sync(FULLMASK, v.y, L);
        }
        p[j] = v;
    }
}

// U3 direct 2x2 (scalar FMA path; tb compile-time for reg targets, hoisted for lane targets)
template<int TL, int TM>
__device__ __forceinline__ void u3_gate(C2 st[8], int lane, const C2* m){
    float4 q0 = *(const float4*)(m);      // m00r, 0, m01.x, m01.y
    float4 q1 = *(const float4*)(m + 2);  // m10.x, m10.y, m11.x, m11.y
    C2 p[8]; fetch_partner<TL, TM>(st, p);
#pragma unroll
    for (int j = 0; j < 8; j++){
        bool tb = (((lane & TL) | (j & TM)) != 0);
        float ax = tb ? q1.z : q0.x;
        float ay = tb ? q1.w : 0.f;
        float bx = tb ? q1.x : q0.z;
        float by = tb ? q1.y : q0.w;
        C2 n;
        n.x = ax*st[j].x - ay*st[j].y + bx*p[j].x - by*p[j].y;
        n.y = ax*st[j].y + ay*st[j].x + bx*p[j].y + by*p[j].x;
        st[j] = n;
    }
}

// Z3 -> reg bit 2, Z7 -> reg bit 1 signs (post-remap). Packed pair reduction.
__device__ __forceinline__ void measure(const C2 st[8], float& z3, float& z7){
    C2 acc{0.f, 0.f};   // x=a3, y=a7
#pragma unroll
    for (int j = 0; j < 8; j++){
        float pr = st[j].x*st[j].x + st[j].y*st[j].y;
        acc.x += (j & 2) ? -pr : pr;
        acc.y += (j & 1) ? -pr : pr;
    }
#pragma unroll
    for (int o = 16; o; o >>= 1){
        C2 t;
        t.x = __shfl_xor_sync(FULLMASK, acc.x, o);
        t.y = __shfl_xor_sync(FULLMASK, acc.y, o);
        acc = padd(acc, t);
    }
    z3 = acc.x; z7 = acc.y;
}

// ── Branch-phase wire map (after w3<->w6 swap) ──
//  lanes: w0:16  w1:8  w2:4  w6:2  w4:1     regs: w5:4  w3:2  w7:1
__device__ __forceinline__ void run_branch_x(const C2 base[8], int lane,
        const float* crc, const float* crs, const C2* u3m, float& z3, float& z7){
    C2 st[8];
#pragma unroll
    for (int j = 0; j < 8; j++) st[j] = base[j];
#define CRXG(TL,TM,CM, CLBIT, i) { \
        float cc, ss; \
        if (CLBIT){ bool ct = (lane & (CLBIT)) != 0; cc = ct ? crc[i] : 1.f; ss = ct ? crs[i] : 0.f; } \
        else { cc = crc[i]; ss = crs[i]; } \
        cr_packed<TL,TM,CM,true>(st, C2{cc,cc}, C2{ss,-ss}); }
    CRXG(8,0,0, 16, 0)   // (0,1)
    CRXG(0,2,0,  4, 1)   // (2,3)
    CRXG(0,4,0,  1, 2)   // (4,5)
    CRXG(0,1,0,  2, 3)   // (6,7)
    CRXG(4,0,0,  8, 4)   // (1,2)
    CRXG(1,0,2,  0, 5)   // (3,4)
    CRXG(2,0,4,  0, 6)   // (5,6)
    u3_gate<8,0>(st, lane, u3m + 0*4);
    u3_gate<0,2>(st, lane, u3m + 1*4);
    u3_gate<0,4>(st, lane, u3m + 2*4);
    u3_gate<0,1>(st, lane, u3m + 3*4);
    CRXG(0,2,0,  8, 7)   // (1,3)
    CRXG(0,1,4,  0, 8)   // (5,7)
    CRXG(0,4,2,  0, 9)   // (3,5)
#undef CRXG
    u3_gate<0,2>(st, lane, u3m + 4*4);
    u3_gate<0,1>(st, lane, u3m + 5*4);
    measure(st, z3, z7);
}

__device__ __forceinline__ void run_branch_y(const C2 base[8], int lane,
        const float* crc, const float* crs, const C2* u3m, float& z3, float& z7){
    C2 st[8];
#pragma unroll
    for (int j = 0; j < 8; j++) st[j] = base[j];
    // lane-target CRY: fold ctrl + tb sign into per-lane coeffs
#define CRYL(TL,CM, CLBIT, i) { \
        float cc, ss; \
        float sel = (lane & (TL)) ? crs[i] : -crs[i]; \
        if (CLBIT){ bool ct = (lane & (CLBIT)) != 0; cc = ct ? crc[i] : 1.f; ss = ct ? sel : 0.f; } \
        else { cc = crc[i]; ss = sel; } \
        cr_packed<TL,0,CM,false>(st, C2{cc,cc}, C2{ss,ss}); }
    // reg-target CRY: per-j sign; ctrl folded (lane) or compile-time (reg)
#define CRYR(TM,CM, CLBIT, i) { \
        float cc, ssp; \
        if (CLBIT){ bool ct = (lane & (CLBIT)) != 0; cc = ct ? crc[i] : 1.f; ssp = ct ? crs[i] : 0.f; } \
        else { cc = crc[i]; ssp = crs[i]; } \
        cry_reg<TM,CM>(st, C2{cc,cc}, C2{ssp,ssp}, C2{-ssp,-ssp}); }
    CRYL(8,0, 16, 0)   // (0,1)
    CRYR(2,0,  4, 1)   // (2,3)
    CRYR(4,0,  1, 2)   // (4,5)
    CRYR(1,0,  2, 3)   // (6,7)
    CRYL(4,0,  8, 4)   // (1,2)
    CRYL(1,2,  0, 5)   // (3,4)
    CRYL(2,4,  0, 6)   // (5,6)
    u3_gate<8,0>(st, lane, u3m + 0*4);
    u3_gate<0,2>(st, lane, u3m + 1*4);
    u3_gate<0,4>(st, lane, u3m + 2*4);
    u3_gate<0,1>(st, lane, u3m + 3*4);
    CRYR(2,0,  8, 7)   // (1,3)
    CRYR(1,4,  0, 8)   // (5,7)
    CRYR(4,2,  0, 9)   // (3,5)
#undef CRYL
#undef CRYR
    u3_gate<0,2>(st, lane, u3m + 4*4);
    u3_gate<0,1>(st, lane, u3m + 5*4);
    measure(st, z3, z7);
}

// CRZ branch: diagonal CR layers -> two precomputed phase tables (packed cmul).
__device__ __forceinline__ void run_branch_z(const C2 base[8], int lane,
        const C2* phA, const C2* phB, const C2* u3m, float& z3, float& z7){
    C2 st[8];
#pragma unroll
    for (int j = 0; j < 8; j++){
        C2 w = phA[j*32 + lane];
        st[j] = pp2(C2{w.x,w.x}, base[j], C2{-w.y,w.y}, C2{base[j].y, base[j].x});
    }
    u3_gate<8,0>(st, lane, u3m + 0*4);
    u3_gate<0,2>(st, lane, u3m + 1*4);
    u3_gate<0,4>(st, lane, u3m + 2*4);
    u3_gate<0,1>(st, lane, u3m + 3*4);
#pragma unroll
    for (int j = 0; j < 8; j++){
        C2 w = phB[j*32 + lane];
        st[j] = pp2(C2{w.x,w.x}, st[j], C2{-w.y,w.y}, C2{st[j].y, st[j].x});
    }
    u3_gate<0,2>(st, lane, u3m + 4*4);
    u3_gate<0,1>(st, lane, u3m + 5*4);
    measure(st, z3, z7);
}

__global__ void __launch_bounds__(256)
qcnn_kernel(const float* __restrict__ theta, const float* __restrict__ phi,
            const float* __restrict__ crw, const float* __restrict__ u3p,
            const float* __restrict__ W1, const float* __restrict__ b1,
            const float* __restrict__ W2, const float* __restrict__ b2,
            float* __restrict__ out, int n)
{
    __shared__ float s_crc[10], s_crs[10];
    __shared__ C2 s_u3[18*4];             // per gate: {m00r,0},{m01},{m10},{m11}
    __shared__ float s_W1[72], s_b1[12], s_W2[12], s_b2;
    __shared__ C2 s_phA[256], s_phB[256]; // CRZ diag phases, [j][lane] (post-remap)

    int tid = threadIdx.x;
    if (tid < 10){
        float t = 0.5f * crw[tid];
        s_crc[tid] = cosf(t);
        s_crs[tid] = sinf(t);
    } else if (tid >= 32 && tid < 50){
        int g = tid - 32;   // branch*6 + gate
        float t  = u3p[g*3+0], ph = u3p[g*3+1], la = u3p[g*3+2];
        float ct, stt; sincosf(0.5f*t, &stt, &ct);
        float cl, sl;  sincosf(la,     &sl,  &cl);
        float cp, sp;  sincosf(ph,     &sp,  &cp);
        s_u3[g*4+0] = C2{ct, 0.f};
        s_u3[g*4+1] = C2{-cl*stt, -sl*stt};
        s_u3[g*4+2] = C2{cp*stt,  sp*stt};
        s_u3[g*4+3] = C2{(cp*cl - sp*sl)*ct, (cp*sl + sp*cl)*ct};
    } else if (tid >= 64 && tid < 136)  s_W1[tid-64]  = W1[tid-64];
    else if (tid >= 160 && tid < 172)   s_b1[tid-160] = b1[tid-160];
    else if (tid >= 176 && tid < 188)   s_W2[tid-176] = W2[tid-176];
    else if (tid == 200)                s_b2 = b2[0];
    __syncthreads();

    // CRZ phase tables. Amplitude a = tid, wire w bit = (a >> (7-w)) & 1.
    // Post-remap storage: lane = w0<<4|w1<<3|w2<<2|w6<<1|w4 ; j = w5<<2|w3<<1|w7
    {
        int a = tid;
        C2 pA{1.f, 0.f}, pB{1.f, 0.f};
#define CRZF(P, cw, tw, i) \
        if ((a >> (7-(cw))) & 1){ \
            float ss = ((a >> (7-(tw))) & 1) ? s_crs[i] : -s_crs[i]; \
            P = cmul(P, C2{s_crc[i], ss}); \
        }
        CRZF(pA, 0,1, 0) CRZF(pA, 2,3, 1) CRZF(pA, 4,5, 2) CRZF(pA, 6,7, 3)
        CRZF(pA, 1,2, 4) CRZF(pA, 3,4, 5) CRZF(pA, 5,6, 6)
        CRZF(pB, 1,3, 7) CRZF(pB, 5,7, 8) CRZF(pB, 3,5, 9)
#undef CRZF
        int w0=(a>>7)&1, w1=(a>>6)&1, w2=(a>>5)&1, w3=(a>>4)&1;
        int w4=(a>>3)&1, w5=(a>>2)&1, w6=(a>>1)&1, w7=a&1;
        int ln = (w0<<4)|(w1<<3)|(w2<<2)|(w6<<1)|w4;
        int jj = (w5<<2)|(w3<<1)|w7;
        s_phA[jj*32 + ln] = pA;
        s_phB[jj*32 + ln] = pB;
    }
    __syncthreads();

    int lane = tid & 31;
    int sample = blockIdx.x * 8 + (tid >> 5);
    if (sample >= n) return;

    float th = theta[sample], fi = phi[sample];
    float cth, sth; __sincosf(th, &sth, &cth);
    C2 vrc{cth, cth}, vrs{sth, -sth};

    // RZ layer = diag phase e^{i*phi*(2*popc(a)-8)} (loop map: w0-4 lanes, w5-7 regs)
    C2 z; __sincosf(2.f*fi, &z.y, &z.x);
    int pcl = __popc(lane);
    C2 wk[4];
    __sincosf(2.f*fi*(float)(pcl - 4), &wk[0].y, &wk[0].x);
    wk[1] = cmul(wk[0], z);
    wk[2] = cmul(wk[1], z);
    wk[3] = cmul(wk[2], z);
    C2 wx[4], wyn[4];
#pragma unroll
    for (int k = 0; k < 4; k++){ wx[k] = C2{wk[k].x, wk[k].x}; wyn[k] = C2{-wk[k].y, wk[k].y}; }

    C2 st[8];
#pragma unroll
    for (int j = 0; j < 8; j++) st[j] = C2{0.0625f, 0.f};

    const int pcj[8] = {0,1,1,2,1,2,2,3};
#pragma unroll 1
    for (int cyc = 0; cyc < 4; cyc++){
#pragma unroll
        for (int j = 0; j < 8; j++)
            st[j] = pp2(wx[pcj[j]], st[j], wyn[pcj[j]], C2{st[j].y, st[j].x});
        // Loop map: w0:16 w1:8 w2:4 w3:2 w4:1 | w5:4 w6:2 w7:1
        cr_packed<24,0,0,true>(st, vrc, vrs);  // (0,1)
        cr_packed< 6,0,0,true>(st, vrc, vrs);  // (2,3)
        cr_packed< 1,4,0,true>(st, vrc, vrs);  // (4,5)
        cr_packed< 0,3,0,true>(st, vrc, vrs);  // (6,7)
        cr_packed<12,0,0,true>(st, vrc, vrs);  // (1,2)
        cr_packed< 3,0,0,true>(st, vrc, vrs);  // (3,4)
        cr_packed< 0,6,0,true>(st, vrc, vrs);  // (5,6)
    }

    // Remap: swap wire 3 (lane bit 2) <-> wire 6 (reg bit 2). 8 shuffles.
#pragma unroll
    for (int j0i = 0; j0i < 4; j0i++){
        const int j0 = (j0i & 1) | ((j0i & 2) << 1);  // {0,1,4,5}
        const int jh = j0 | 2;
        bool hi = (lane & 2) != 0;
        C2 send = hi ? st[j0] : st[jh];
        send.x = __shfl_xor_sync(FULLMASK, send.x, 2);
        send.y = __shfl_xor_sync(FULLMASK, send.y, 2);
        if (hi) st[j0] = send; else st[jh] = send;
    }

    float feat[6];
    run_branch_x(st, lane, s_crc, s_crs, s_u3 + 0,   feat[0], feat[1]);
    run_branch_y(st, lane, s_crc, s_crs, s_u3 + 24,  feat[2], feat[3]);
    run_branch_z(st, lane, s_phA, s_phB, s_u3 + 48,  feat[4], feat[5]);

    if (lane == 0){
        float acc = s_b2;
#pragma unroll
        for (int k = 0; k < 12; k++){
            float u = s_b1[k];
#pragma unroll
            for (int i = 0; i < 6; i++) u += s_W1[k*6+i] * feat[i];
            float e = __expf(2.f*u);                 // tanh via exp
            acc += s_W2[k] * (1.f - __fdividef(2.f, e + 1.f));
        }
        out[sample] = __fdividef(1.f, 1.f + __expf(-acc));
    }
}

extern "C" void kernel_launch(void* const* d_in, const int* in_sizes, int n_in,
                              void* d_out, int out_size)
{
    const float* theta = (const float*)d_in[0];
    const float* phi   = (const float*)d_in[1];
    const float* crw   = (const float*)d_in[2];
    const float* u3p   = (const float*)d_in[3];
    const float* W1    = (const float*)d_in[4];
    const float* b1    = (const float*)d_in[5];
    const float* W2    = (const float*)d_in[6];
    const float* b2    = (const float*)d_in[7];
    float* out = (float*)d_out;
    int n = in_sizes[0];
    int blocks = (n + 7) / 8;
    qcnn_kernel<<<blocks, 256>>>(theta, phi, crw, u3p, W1, b1, W2, b2, out, n);
}

// round 7
// speedup vs baseline: 1.3856x; 1.0347x over previous
#include <cuda_runtime.h>

#define FULLMASK 0xffffffffu

struct alignas(8) C2 { float x, y; };

__device__ __forceinline__ C2 cmul(C2 a, C2 b){
    C2 r; r.x = a.x*b.x - a.y*b.y; r.y = a.x*b.y + a.y*b.x; return r;
}

// d = vc (.) s + vs (.) p   (packed: 1 mul + 1 fma)
__device__ __forceinline__ C2 pp2(C2 vc, C2 s, C2 vs, C2 p){
    C2 d;
    asm("{\n\t"
        ".reg .b64 t0, t1, t2, t3;\n\t"
        "mov.b64 t0, {%2,%3};\n\t"
        "mov.b64 t1, {%4,%5};\n\t"
        "mov.b64 t2, {%6,%7};\n\t"
        "mov.b64 t3, {%8,%9};\n\t"
        "mul.rn.f32x2 t2, t2, t3;\n\t"
        "fma.rn.f32x2 t0, t0, t1, t2;\n\t"
        "mov.b64 {%0,%1}, t0;\n\t"
        "}"
        : "=f"(d.x), "=f"(d.y)
        : "f"(vc.x),"f"(vc.y),"f"(s.x),"f"(s.y),
          "f"(vs.x),"f"(vs.y),"f"(p.x),"f"(p.y));
    return d;
}

// Full complex 2x2 row: d = va(.)s + vb(.)s_swap + vc(.)p + ve(.)p_swap
__device__ __forceinline__ C2 pp4(C2 va, C2 s, C2 vb, C2 vc_, C2 p, C2 ve){
    C2 d;
    asm("{\n\t"
        ".reg .b64 r0, r1, r2, r3, r4, r5, r6, r7;\n\t"
        "mov.b64 r0, {%2,%3};\n\t"    // va
        "mov.b64 r1, {%4,%5};\n\t"    // s
        "mov.b64 r2, {%5,%4};\n\t"    // s swapped
        "mov.b64 r3, {%6,%7};\n\t"    // vb
        "mov.b64 r4, {%8,%9};\n\t"    // vc
        "mov.b64 r5, {%10,%11};\n\t"  // p
        "mov.b64 r6, {%11,%10};\n\t"  // p swapped
        "mov.b64 r7, {%12,%13};\n\t"  // ve
        "mul.rn.f32x2 r0, r0, r1;\n\t"
        "fma.rn.f32x2 r0, r3, r2, r0;\n\t"
        "fma.rn.f32x2 r0, r4, r5, r0;\n\t"
        "fma.rn.f32x2 r0, r7, r6, r0;\n\t"
        "mov.b64 {%0,%1}, r0;\n\t"
        "}"
        : "=f"(d.x), "=f"(d.y)
        : "f"(va.x),"f"(va.y), "f"(s.x),"f"(s.y), "f"(vb.x),"f"(vb.y),
          "f"(vc_.x),"f"(vc_.y), "f"(p.x),"f"(p.y), "f"(ve.x),"f"(ve.y));
    return d;
}

// 3-term (diag coeff real): d = (ax,ax)(.)s + vc(.)p + ve(.)p_swap
__device__ __forceinline__ C2 pp3(float ax, C2 s, C2 vc_, C2 p, C2 ve){
    C2 d;
    asm("{\n\t"
        ".reg .b64 r0, r1, r2, r3, r4, r5;\n\t"
        "mov.b64 r0, {%2,%2};\n\t"    // (ax,ax)
        "mov.b64 r1, {%3,%4};\n\t"    // s
        "mov.b64 r2, {%5,%6};\n\t"    // vc
        "mov.b64 r3, {%7,%8};\n\t"    // p
        "mov.b64 r4, {%8,%7};\n\t"    // p swapped
        "mov.b64 r5, {%9,%10};\n\t"   // ve
        "mul.rn.f32x2 r0, r0, r1;\n\t"
        "fma.rn.f32x2 r0, r2, r3, r0;\n\t"
        "fma.rn.f32x2 r0, r5, r4, r0;\n\t"
        "mov.b64 {%0,%1}, r0;\n\t"
        "}"
        : "=f"(d.x), "=f"(d.y)
        : "f"(ax), "f"(s.x),"f"(s.y), "f"(vc_.x),"f"(vc_.y),
          "f"(p.x),"f"(p.y), "f"(ve.x),"f"(ve.y));
    return d;
}

__device__ __forceinline__ C2 padd(C2 a, C2 b){
    C2 d;
    asm("{\n\t"
        ".reg .b64 t0, t1;\n\t"
        "mov.b64 t0, {%2,%3};\n\t"
        "mov.b64 t1, {%4,%5};\n\t"
        "add.rn.f32x2 t0, t0, t1;\n\t"
        "mov.b64 {%0,%1}, t0;\n\t"
        "}"
        : "=f"(d.x), "=f"(d.y)
        : "f"(a.x),"f"(a.y),"f"(b.x),"f"(b.y));
    return d;
}

// Packed CR-style gate (in place): st[j] = vc(.)st[j] + vs(.)partner
template<int TL, int TM, int CM, bool SWAP>
__device__ __forceinline__ void cr_packed(C2 st[8], C2 vc, C2 vs){
    C2 p[8];
#pragma unroll
    for (int j = 0; j < 8; j++){
        if (CM == 0 || (j & CM)){
            C2 v = st[j ^ TM];
            if (SWAP){ float t = v.x; v.x = v.y; v.y = t; }
            if (TL){
                v.x = __shfl_xor_sync(FULLMASK, v.x, TL);
                v.y = __shfl_xor_sync(FULLMASK, v.y, TL);
            }
            p[j] = v;
        }
    }
#pragma unroll
    for (int j = 0; j < 8; j++)
        if (CM == 0 || (j & CM)) st[j] = pp2(vc, st[j], vs, p[j]);
}

// Same, but reads src and writes st (folds the branch base copy into gate 0).
template<int TL, int TM, bool SWAP>
__device__ __forceinline__ void cr_packed_g(const C2 src[8], C2 st[8], C2 vc, C2 vs){
    C2 p[8];
#pragma unroll
    for (int j = 0; j < 8; j++){
        C2 v = src[j ^ TM];
        if (SWAP){ float t = v.x; v.x = v.y; v.y = t; }
        if (TL){
            v.x = __shfl_xor_sync(FULLMASK, v.x, TL);
            v.y = __shfl_xor_sync(FULLMASK, v.y, TL);
        }
        p[j] = v;
    }
#pragma unroll
    for (int j = 0; j < 8; j++) st[j] = pp2(vc, src[j], vs, p[j]);
}

// CRY on a register-target bit: sign of vs depends on j&TM (compile time).
template<int TM, int CM>
__device__ __forceinline__ void cry_reg(C2 st[8], C2 vc, C2 vsp, C2 vsm){
    C2 p[8];
#pragma unroll
    for (int j = 0; j < 8; j++)
        if (CM == 0 || (j & CM)) p[j] = st[j ^ TM];
#pragma unroll
    for (int j = 0; j < 8; j++)
        if (CM == 0 || (j & CM)) st[j] = pp2(vc, st[j], (j & TM) ? vsp : vsm, p[j]);
}

template<int L, int M>
__device__ __forceinline__ void fetch_partner(const C2 st[8], C2 p[8]){
#pragma unroll
    for (int j = 0; j < 8; j++){
        C2 v = st[j ^ M];
        if constexpr (L != 0){
            v.x = __shfl_xor_sync(FULLMASK, v.x, L);
            v.y = __shfl_xor_sync(FULLMASK, v.y, L);
        }
        p[j] = v;
    }
}

// U3 packed: n = a (x) s + b (x) p  (complex 2x2 row), coefficients hoisted.
template<int TL, int TM>
__device__ __forceinline__ void u3_gate(C2 st[8], int lane, const C2* m){
    float4 q0 = *(const float4*)(m);      // m00r, 0, m01.x, m01.y
    float4 q1 = *(const float4*)(m + 2);  // m10.x, m10.y, m11.x, m11.y
    C2 p[8]; fetch_partner<TL, TM>(st, p);
    if constexpr (TL != 0){
        bool tb = (lane & TL) != 0;
        float ax = tb ? q1.z : q0.x;
        float ay = tb ? q1.w : 0.f;
        float bx = tb ? q1.x : q0.z;
        float by = tb ? q1.y : q0.w;
        C2 va{ax,ax}, vb{-ay,ay}, vc_{bx,bx}, ve{-by,by};
#pragma unroll
        for (int j = 0; j < 8; j++)
            st[j] = pp4(va, st[j], vb, vc_, p[j], ve);
    } else {
        C2 va1{q1.z,q1.z}, vb1{-q1.w,q1.w}, vc1{q1.x,q1.x}, ve1{-q1.y,q1.y};
        C2 vc0{q0.z,q0.z}, ve0{-q0.w,q0.w};
#pragma unroll
        for (int j = 0; j < 8; j++){
            if (j & TM) st[j] = pp4(va1, st[j], vb1, vc1, p[j], ve1);
            else        st[j] = pp3(q0.x, st[j], vc0, p[j], ve0);
        }
    }
}

// Z3 -> reg bit 2, Z7 -> reg bit 1 signs (post-remap). Packed pair reduction.
__device__ __forceinline__ void measure(const C2 st[8], float& z3, float& z7){
    C2 acc{0.f, 0.f};   // x=a3, y=a7
#pragma unroll
    for (int j = 0; j < 8; j++){
        float pr = st[j].x*st[j].x + st[j].y*st[j].y;
        acc.x += (j & 2) ? -pr : pr;
        acc.y += (j & 1) ? -pr : pr;
    }
#pragma unroll
    for (int o = 16; o; o >>= 1){
        C2 t;
        t.x = __shfl_xor_sync(FULLMASK, acc.x, o);
        t.y = __shfl_xor_sync(FULLMASK, acc.y, o);
        acc = padd(acc, t);
    }
    z3 = acc.x; z7 = acc.y;
}

// ── Branch-phase wire map (after w3<->w6 swap) ──
//  lanes: w0:16  w1:8  w2:4  w6:2  w4:1     regs: w5:4  w3:2  w7:1
__device__ __forceinline__ void run_branch_x(const C2 base[8], int lane,
        const float* crc, const float* crs, const C2* u3m, float& z3, float& z7){
    C2 st[8];
#define CRXC(CLBIT, i) \
        float cc, ss; \
        if (CLBIT){ bool ct = (lane & (CLBIT)) != 0; cc = ct ? crc[i] : 1.f; ss = ct ? crs[i] : 0.f; } \
        else { cc = crc[i]; ss = crs[i]; }
    { CRXC(16, 0) cr_packed_g<8,0,true>(base, st, C2{cc,cc}, C2{ss,-ss}); }   // (0,1)
#define CRXG(TL,TM,CM, CLBIT, i) { CRXC(CLBIT, i) cr_packed<TL,TM,CM,true>(st, C2{cc,cc}, C2{ss,-ss}); }
    CRXG(0,2,0,  4, 1)   // (2,3)
    CRXG(0,4,0,  1, 2)   // (4,5)
    CRXG(0,1,0,  2, 3)   // (6,7)
    CRXG(4,0,0,  8, 4)   // (1,2)
    CRXG(1,0,2,  0, 5)   // (3,4)
    CRXG(2,0,4,  0, 6)   // (5,6)
    u3_gate<8,0>(st, lane, u3m + 0*4);
    u3_gate<0,2>(st, lane, u3m + 1*4);
    u3_gate<0,4>(st, lane, u3m + 2*4);
    u3_gate<0,1>(st, lane, u3m + 3*4);
    CRXG(0,2,0,  8, 7)   // (1,3)
    CRXG(0,1,4,  0, 8)   // (5,7)
    CRXG(0,4,2,  0, 9)   // (3,5)
#undef CRXG
#undef CRXC
    u3_gate<0,2>(st, lane, u3m + 4*4);
    u3_gate<0,1>(st, lane, u3m + 5*4);
    measure(st, z3, z7);
}

__device__ __forceinline__ void run_branch_y(const C2 base[8], int lane,
        const float* crc, const float* crs, const C2* u3m, float& z3, float& z7){
    C2 st[8];
    // first gate (0,1): lane target TL8, ctrl lane16 — fold, read from base
    {
        float sel = (lane & 8) ? crs[0] : -crs[0];
        bool ct = (lane & 16) != 0;
        float cc = ct ? crc[0] : 1.f;
        float ss = ct ? sel : 0.f;
        cr_packed_g<8,0,false>(base, st, C2{cc,cc}, C2{ss,ss});
    }
#define CRYL(TL,CM, CLBIT, i) { \
        float cc, ss; \
        float sel = (lane & (TL)) ? crs[i] : -crs[i]; \
        if (CLBIT){ bool ct = (lane & (CLBIT)) != 0; cc = ct ? crc[i] : 1.f; ss = ct ? sel : 0.f; } \
        else { cc = crc[i]; ss = sel; } \
        cr_packed<TL,0,CM,false>(st, C2{cc,cc}, C2{ss,ss}); }
#define CRYR(TM,CM, CLBIT, i) { \
        float cc, ssp; \
        if (CLBIT){ bool ct = (lane & (CLBIT)) != 0; cc = ct ? crc[i] : 1.f; ssp = ct ? crs[i] : 0.f; } \
        else { cc = crc[i]; ssp = crs[i]; } \
        cry_reg<TM,CM>(st, C2{cc,cc}, C2{ssp,ssp}, C2{-ssp,-ssp}); }
    CRYR(2,0,  4, 1)   // (2,3)
    CRYR(4,0,  1, 2)   // (4,5)
    CRYR(1,0,  2, 3)   // (6,7)
    CRYL(4,0,  8, 4)   // (1,2)
    CRYL(1,2,  0, 5)   // (3,4)
    CRYL(2,4,  0, 6)   // (5,6)
    u3_gate<8,0>(st, lane, u3m + 0*4);
    u3_gate<0,2>(st, lane, u3m + 1*4);
    u3_gate<0,4>(st, lane, u3m + 2*4);
    u3_gate<0,1>(st, lane, u3m + 3*4);
    CRYR(2,0,  8, 7)   // (1,3)
    CRYR(1,4,  0, 8)   // (5,7)
    CRYR(4,2,  0, 9)   // (3,5)
#undef CRYL
#undef CRYR
    u3_gate<0,2>(st, lane, u3m + 4*4);
    u3_gate<0,1>(st, lane, u3m + 5*4);
    measure(st, z3, z7);
}

// CRZ branch: diagonal CR layers -> two precomputed phase tables (packed cmul).
__device__ __forceinline__ void run_branch_z(const C2 base[8], int lane,
        const C2* phA, const C2* phB, const C2* u3m, float& z3, float& z7){
    C2 st[8];
#pragma unroll
    for (int j = 0; j < 8; j++){
        C2 w = phA[j*32 + lane];
        st[j] = pp2(C2{w.x,w.x}, base[j], C2{-w.y,w.y}, C2{base[j].y, base[j].x});
    }
    u3_gate<8,0>(st, lane, u3m + 0*4);
    u3_gate<0,2>(st, lane, u3m + 1*4);
    u3_gate<0,4>(st, lane, u3m + 2*4);
    u3_gate<0,1>(st, lane, u3m + 3*4);
#pragma unroll
    for (int j = 0; j < 8; j++){
        C2 w = phB[j*32 + lane];
        st[j] = pp2(C2{w.x,w.x}, st[j], C2{-w.y,w.y}, C2{st[j].y, st[j].x});
    }
    u3_gate<0,2>(st, lane, u3m + 4*4);
    u3_gate<0,1>(st, lane, u3m + 5*4);
    measure(st, z3, z7);
}

__global__ void __launch_bounds__(128, 5)
qcnn_kernel(const float* __restrict__ theta, const float* __restrict__ phi,
            const float* __restrict__ crw, const float* __restrict__ u3p,
            const float* __restrict__ W1, const float* __restrict__ b1,
            const float* __restrict__ W2, const float* __restrict__ b2,
            float* __restrict__ out, int n)
{
    __shared__ float s_crc[10], s_crs[10];
    __shared__ C2 s_u3[18*4];             // per gate: {m00r,0},{m01},{m10},{m11}
    __shared__ float s_W1[72], s_b1[12], s_W2[12], s_b2;
    __shared__ C2 s_phA[256], s_phB[256]; // CRZ diag phases, [j][lane] (post-remap)

    int tid = threadIdx.x;
    if (tid < 72)                         s_W1[tid]     = W1[tid];
    else if (tid < 84)                    s_b1[tid-72]  = b1[tid-72];
    else if (tid < 96)                    s_W2[tid-84]  = W2[tid-84];
    else if (tid == 96)                   s_b2          = b2[0];
    else if (tid >= 98 && tid < 108){
        int i = tid - 98;
        float t = 0.5f * crw[i];
        s_crc[i] = cosf(t);
        s_crs[i] = sinf(t);
    } else if (tid >= 108 && tid < 126){
        int g = tid - 108;   // branch*6 + gate
        float t  = u3p[g*3+0], ph = u3p[g*3+1], la = u3p[g*3+2];
        float ct, stt; sincosf(0.5f*t, &stt, &ct);
        float cl, sl;  sincosf(la,     &sl,  &cl);
        float cp, sp;  sincosf(ph,     &sp,  &cp);
        s_u3[g*4+0] = C2{ct, 0.f};
        s_u3[g*4+1] = C2{-cl*stt, -sl*stt};
        s_u3[g*4+2] = C2{cp*stt,  sp*stt};
        s_u3[g*4+3] = C2{(cp*cl - sp*sl)*ct, (cp*sl + sp*cl)*ct};
    }
    __syncthreads();

    // CRZ phase tables (2 passes, 128 threads). Wire w bit of a = (a >> (7-w)) & 1.
    // Post-remap storage: lane = w0<<4|w1<<3|w2<<2|w6<<1|w4 ; j = w5<<2|w3<<1|w7
#pragma unroll
    for (int a = tid; a < 256; a += 128){
        C2 pA{1.f, 0.f}, pB{1.f, 0.f};
#define CRZF(P, cw, tw, i) \
        if ((a >> (7-(cw))) & 1){ \
            float ss = ((a >> (7-(tw))) & 1) ? s_crs[i] : -s_crs[i]; \
            P = cmul(P, C2{s_crc[i], ss}); \
        }
        CRZF(pA, 0,1, 0) CRZF(pA, 2,3, 1) CRZF(pA, 4,5, 2) CRZF(pA, 6,7, 3)
        CRZF(pA, 1,2, 4) CRZF(pA, 3,4, 5) CRZF(pA, 5,6, 6)
        CRZF(pB, 1,3, 7) CRZF(pB, 5,7, 8) CRZF(pB, 3,5, 9)
#undef CRZF
        int w0=(a>>7)&1, w1=(a>>6)&1, w2=(a>>5)&1, w3=(a>>4)&1;
        int w4=(a>>3)&1, w5=(a>>2)&1, w6=(a>>1)&1, w7=a&1;
        int ln = (w0<<4)|(w1<<3)|(w2<<2)|(w6<<1)|w4;
        int jj = (w5<<2)|(w3<<1)|w7;
        s_phA[jj*32 + ln] = pA;
        s_phB[jj*32 + ln] = pB;
    }
    __syncthreads();

    int lane = tid & 31;
    int sample = blockIdx.x * 4 + (tid >> 5);
    if (sample >= n) return;

    float th = theta[sample], fi = phi[sample];
    float cth, sth; __sincosf(th, &sth, &cth);
    C2 vrc{cth, cth}, vrs{sth, -sth};

    // RZ layer = diag phase e^{i*phi*(2*popc(a)-8)} (loop map: w0-4 lanes, w5-7 regs)
    C2 z; __sincosf(2.f*fi, &z.y, &z.x);
    int pcl = __popc(lane);
    C2 wk[4];
    __sincosf(2.f*fi*(float)(pcl - 4), &wk[0].y, &wk[0].x);
    wk[1] = cmul(wk[0], z);
    wk[2] = cmul(wk[1], z);
    wk[3] = cmul(wk[2], z);
    C2 wx[4], wyn[4];
#pragma unroll
    for (int k = 0; k < 4; k++){ wx[k] = C2{wk[k].x, wk[k].x}; wyn[k] = C2{-wk[k].y, wk[k].y}; }

    C2 st[8];
#pragma unroll
    for (int j = 0; j < 8; j++) st[j] = C2{0.0625f, 0.f};

    const int pcj[8] = {0,1,1,2,1,2,2,3};
#pragma unroll 1
    for (int cyc = 0; cyc < 4; cyc++){
#pragma unroll
        for (int j = 0; j < 8; j++)
            st[j] = pp2(wx[pcj[j]], st[j], wyn[pcj[j]], C2{st[j].y, st[j].x});
        // Loop map: w0:16 w1:8 w2:4 w3:2 w4:1 | w5:4 w6:2 w7:1
        cr_packed<24,0,0,true>(st, vrc, vrs);  // (0,1)
        cr_packed< 6,0,0,true>(st, vrc, vrs);  // (2,3)
        cr_packed< 1,4,0,true>(st, vrc, vrs);  // (4,5)
        cr_packed< 0,3,0,true>(st, vrc, vrs);  // (6,7)
        cr_packed<12,0,0,true>(st, vrc, vrs);  // (1,2)
        cr_packed< 3,0,0,true>(st, vrc, vrs);  // (3,4)
        cr_packed< 0,6,0,true>(st, vrc, vrs);  // (5,6)
    }

    // Remap: swap wire 3 (lane bit 2) <-> wire 6 (reg bit 2). 8 shuffles.
#pragma unroll
    for (int j0i = 0; j0i < 4; j0i++){
        const int j0 = (j0i & 1) | ((j0i & 2) << 1);  // {0,1,4,5}
        const int jh = j0 | 2;
        bool hi = (lane & 2) != 0;
        C2 send = hi ? st[j0] : st[jh];
        send.x = __shfl_xor_sync(FULLMASK, send.x, 2);
        send.y = __shfl_xor_sync(FULLMASK, send.y, 2);
        if (hi) st[j0] = send; else st[jh] = send;
    }

    float feat[6];
    run_branch_x(st, lane, s_crc, s_crs, s_u3 + 0,   feat[0], feat[1]);
    run_branch_y(st, lane, s_crc, s_crs, s_u3 + 24,  feat[2], feat[3]);
    run_branch_z(st, lane, s_phA, s_phB, s_u3 + 48,  feat[4], feat[5]);

    if (lane == 0){
        float acc = s_b2;
#pragma unroll
        for (int k = 0; k < 12; k++){
            float u = s_b1[k];
#pragma unroll
            for (int i = 0; i < 6; i++) u += s_W1[k*6+i] * feat[i];
            float e = __expf(2.f*u);                 // tanh via exp
            acc += s_W2[k] * (1.f - __fdividef(2.f, e + 1.f));
        }
        out[sample] = __fdividef(1.f, 1.f + __expf(-acc));
    }
}

extern "C" void kernel_launch(void* const* d_in, const int* in_sizes, int n_in,
                              void* d_out, int out_size)
{
    const float* theta = (const float*)d_in[0];
    const float* phi   = (const float*)d_in[1];
    const float* crw   = (const float*)d_in[2];
    const float* u3p   = (const float*)d_in[3];
    const float* W1    = (const float*)d_in[4];
    const float* b1    = (const float*)d_in[5];
    const float* W2    = (const float*)d_in[6];
    const float* b2    = (const float*)d_in[7];
    float* out = (float*)d_out;
    int n = in_sizes[0];
    int blocks = (n + 3) / 4;
    qcnn_kernel<<<blocks, 128>>>(theta, phi, crw, u3p, W1, b1, W2, b2, out, n);
}